// round 12
// baseline (speedup 1.0000x reference)
#include <cuda_runtime.h>
#include <cuda_bf16.h>
#include <cstdint>

#define P     96
#define NN    9216
#define THR   0.9f
#define MAXM  1024                 // fast-path capacity (observed M ~ 922)
#define FULLM 0xffffffffu
#define GRID  64
#define BLK   256
#define NTHR  (GRID * BLK)
#define NWARP (NTHR / 32)
#define DSMEM (MAXM * 32 * 4)      // 128KB dynamic smem (aliased per phase)
#define BXOFF 40960                // byte offset of box staging (past 36KB scores)

// device-global scratch (no runtime allocation allowed)
__device__ int      g_cnt;
__device__ __align__(128) int          g_bar_cnt;   // own L2 line
__device__ __align__(128) volatile int g_bar_flag;  // own L2 line
__device__ float    g_sc[NN];
__device__ float4   g_bx[NN];
__device__ __align__(16) uint32_t g_mask32[MAXM * 32];  // row stride 32 = 128B line

// grid-wide barrier (all GRID blocks co-resident; GRID <= SM count)
__device__ __forceinline__ void gbar(int phase)
{
    __syncthreads();
    if (threadIdx.x == 0) {
        __threadfence();
        if (atomicAdd(&g_bar_cnt, 1) == GRID - 1) {
            g_bar_cnt = 0;
            __threadfence();
            g_bar_flag = phase;
        } else {
            while (g_bar_flag < phase) { }
            __threadfence();
        }
    }
    __syncthreads();
}

__device__ __forceinline__ bool iou_gt(const float4 bi, const float ai, const float4 bj)
{
    const float ix1 = fmaxf(bi.x, bj.x);
    const float iy1 = fmaxf(bi.y, bj.y);
    const float ix2 = fminf(bi.z, bj.z);
    const float iy2 = fminf(bi.w, bj.w);
    const float iw = fmaxf(__fsub_rn(ix2, ix1), 0.0f);
    const float ih = fmaxf(__fsub_rn(iy2, iy1), 0.0f);
    const float inter = __fmul_rn(iw, ih);
    const float aj = __fmul_rn(__fsub_rn(bj.z, bj.x), __fsub_rn(bj.w, bj.y));
    const float uni = __fsub_rn(__fadd_rn(ai, aj), inter);
    return (uni > 0.0f) && (__fdiv_rn(inter, uni) > 0.5f);
}

extern __shared__ unsigned char dsm[];   // dynamic smem, aliased per phase

__global__ void __launch_bounds__(BLK) k_all(
    const float* __restrict__ x, float* __restrict__ out, int out_size)
{
    float*    s_sc  = reinterpret_cast<float*>(dsm);             // phase A: all NN scores
    float4*   s_bx  = reinterpret_cast<float4*>(dsm + BXOFF);    // phase B: M boxes
    uint32_t* smask = reinterpret_cast<uint32_t*>(dsm);          // phase C: full mask

    __shared__ uint32_t sdiag[32 * 32];
    __shared__ uint32_t s_keepw[32];
    __shared__ uint32_t s_kb[NN / 32];     // slow-path kept bitmap
    __shared__ int      s_mcnt;

    const int tid  = threadIdx.x;
    const int gtid = blockIdx.x * BLK + tid;
    const int lane = tid & 31;
    const int widx = tid >> 5;
    const int gw   = blockIdx.x * (BLK / 32) + widx;   // global warp id

    // ------ phase A: zero output; rank+decode+scatter directly (no compaction)
    if (tid == 0) s_mcnt = 0;
    for (int i = gtid; i < out_size; i += NTHR) out[i] = 0.0f;
    for (int i = tid; i < NN; i += BLK) s_sc[i] = x[i];
    __syncthreads();

    int nvalid = 0;
    for (int gid = gw; gid < NN; gid += NWARP) {
        const float s = s_sc[gid];             // warp-uniform broadcast
        if (!(s > THR)) continue;              // warp-uniform skip
        ++nvalid;
        // rank over raw scores: validity of j implied (s_j >= s > THR)
        int r = 0;
        #pragma unroll 8
        for (int j = lane; j < NN; j += 32) {
            const float sj = s_sc[j];
            r += (sj > s) || ((sj == s) && (j < gid));
        }
        r = __reduce_add_sync(FULLM, r);
        if (lane == 0) {
            const float fi = (float)(gid / P);
            const float fj = (float)(gid % P);
            const float bx = __fadd_rn(__fmul_rn(x[1 * NN + gid], 16.0f), __fmul_rn(fi, 16.0f));
            const float by = __fadd_rn(__fmul_rn(x[2 * NN + gid], 16.0f), __fmul_rn(fj, 16.0f));
            const float bw = __fmul_rn(x[3 * NN + gid], 1536.0f);
            const float bh = __fmul_rn(x[4 * NN + gid], 1536.0f);
            g_sc[r] = s;
            g_bx[r] = make_float4(rintf(bx), rintf(by),
                                  rintf(__fadd_rn(bw, bx)), rintf(__fadd_rn(bh, by)));
        }
    }
    if (lane == 0 && nvalid) atomicAdd(&s_mcnt, nvalid);
    __syncthreads();
    if (tid == 0 && s_mcnt) atomicAdd(&g_cnt, s_mcnt);
    gbar(1);

    // ------ phase B: suppression mask (smem boxes, ballot) -------------------
    const int M = g_cnt;
    if (M > 0 && M <= MAXM) {
        const int W = (M + 31) >> 5;
        for (int j = tid; j < M; j += BLK) s_bx[j] = g_bx[j];
        __syncthreads();
        for (int i = gw; i < M; i += NWARP) {
            const float4 bi = s_bx[i];
            const float  ai = __fmul_rn(__fsub_rn(bi.z, bi.x), __fsub_rn(bi.w, bi.y));
            uint32_t myword = 0u;
            for (int w = 0; w < W; ++w) {
                const int j = (w << 5) + lane;
                bool pred = false;
                if (j < M) pred = iou_gt(bi, ai, s_bx[j]);
                const uint32_t word = __ballot_sync(FULLM, pred);
                if (lane == w) myword = word;
            }
            g_mask32[i * 32 + lane] = (lane < W) ? myword : 0u;  // full 128B line
        }
    }
    gbar(2);

    // ------ phase C: greedy reduce (block 0 only) ----------------------------
    if (blockIdx.x != 0) return;
    const bool wk = (out_size >= 6 * NN);

    if (M > 0 && M <= MAXM) {
        const int W = (M + 31) >> 5;
        const int words = M * 32;

        // all 8 warps stage the full mask into dynamic smem (uint4 vectorized)
        {
            const uint4* __restrict__ src4 = reinterpret_cast<const uint4*>(g_mask32);
            uint4* dst4 = reinterpret_cast<uint4*>(smask);
            for (int t = tid; t < (words >> 2); t += BLK) dst4[t] = src4[t];
        }
        for (int idx = tid; idx < (W << 5); idx += BLK)
            sdiag[idx] = (idx < M) ? g_mask32[idx * 32 + (idx >> 5)] : 0u;
        __syncthreads();

        if (tid < 32) {
            const uint32_t mybit = 1u << lane;
            const uint32_t above = ~((2u << lane) - 1u);   // bits strictly > lane
            uint32_t rem = 0u;

            for (int w = 0; w < W; ++w) {
                const int base = w << 5;

                uint32_t buf[32];
                #pragma unroll
                for (int b = 0; b < 32; ++b)
                    buf[b] = smask[(base + b) * 32 + lane];

                const int nval = M - base;
                const uint32_t vmask = (nval >= 32) ? FULLM : ((1u << nval) - 1u);
                const uint32_t rem_w = __shfl_sync(FULLM, rem, w);
                const uint32_t cand  = (~rem_w) & vmask;
                const uint32_t d = sdiag[base + lane] & above;

                // Jacobi fixpoint (unroll 2 per convergence check);
                // prefix-stabilization guarantees the greedy fixpoint.
                uint32_t kept = cand;
                for (;;) {
                    uint32_t sup = __reduce_or_sync(FULLM, (kept & mybit) ? d : 0u);
                    const uint32_t k1 = cand & ~sup;
                    sup = __reduce_or_sync(FULLM, (k1 & mybit) ? d : 0u);
                    const uint32_t k2 = cand & ~sup;
                    if (k2 == k1) { kept = k2; break; }
                    if (k2 == kept) break;
                    kept = k2;
                }
                if (lane == 0) s_keepw[w] = kept;

                uint32_t acc = 0u;
                #pragma unroll
                for (int b = 0; b < 32; ++b)
                    acc |= (kept & (1u << b)) ? buf[b] : 0u;
                rem |= acc;
            }
        }
        __syncthreads();

        for (int i = tid; i < M; i += BLK) {
            if ((s_keepw[i >> 5] >> (i & 31)) & 1u) {
                const float4 bi = g_bx[i];
                out[i * 5 + 0] = g_sc[i];
                out[i * 5 + 1] = bi.x;
                out[i * 5 + 2] = bi.y;
                out[i * 5 + 3] = __fsub_rn(bi.z, bi.x);
                out[i * 5 + 4] = __fsub_rn(bi.w, bi.y);
                if (wk) out[5 * NN + i] = 1.0f;
            }
        }
    } else if (M > MAXM) {
        // correct-but-slow fallback (never expected: seed-fixed M ~ 922)
        for (int t = tid; t < NN / 32; t += BLK) s_kb[t] = 0u;
        __syncthreads();
        if (tid == 0) {
            for (int i = 0; i < M; ++i) {
                const float4 bi = g_bx[i];
                const float  ai = __fmul_rn(__fsub_rn(bi.z, bi.x), __fsub_rn(bi.w, bi.y));
                bool sup = false;
                for (int j = 0; j < i && !sup; ++j)
                    if ((s_kb[j >> 5] >> (j & 31)) & 1u)
                        sup = iou_gt(bi, ai, g_bx[j]);
                if (!sup) {
                    s_kb[i >> 5] |= 1u << (i & 31);
                    out[i * 5 + 0] = g_sc[i];
                    out[i * 5 + 1] = bi.x;
                    out[i * 5 + 2] = bi.y;
                    out[i * 5 + 3] = __fsub_rn(bi.z, bi.x);
                    out[i * 5 + 4] = __fsub_rn(bi.w, bi.y);
                    if (wk) out[5 * NN + i] = 1.0f;
                }
            }
        }
        __syncthreads();
    }

    // deterministic state for the next graph replay
    if (tid == 0) { g_cnt = 0; g_bar_flag = 0; }
}

// ---------------------------------------------------------------------------
extern "C" void kernel_launch(void* const* d_in, const int* in_sizes, int n_in,
                              void* d_out, int out_size)
{
    const float* x = (const float*)d_in[0];
    float* out = (float*)d_out;
    cudaFuncSetAttribute(k_all, cudaFuncAttributeMaxDynamicSharedMemorySize, DSMEM);
    k_all<<<GRID, BLK, DSMEM>>>(x, out, out_size);
}

// round 13
// speedup vs baseline: 1.0006x; 1.0006x over previous
#include <cuda_runtime.h>
#include <cuda_bf16.h>
#include <cstdint>

#define P     96
#define NN    9216
#define THR   0.9f
#define MAXM  1024                 // fast-path capacity (observed M ~ 922)
#define FULLM 0xffffffffu
#define GRID  64
#define BLK   256
#define NTHR  (GRID * BLK)
#define NWARP (NTHR / 32)
#define DSMEM (MAXM * 32 * 4)      // 128KB dynamic smem (aliased per phase)
#define BXOFF 40960                // byte offset of box staging (past 36KB scores)

// device-global scratch (no runtime allocation allowed)
__device__ int      g_cnt;
__device__ __align__(128) int          g_bar_cnt;   // own L2 line
__device__ __align__(128) volatile int g_bar_flag;  // own L2 line
__device__ float    g_sc[NN];
__device__ float4   g_bx[NN];
__device__ __align__(16) uint32_t g_mask32[MAXM * 32];  // row stride 32 = 128B line

// grid-wide barrier (all GRID blocks co-resident; GRID <= SM count)
__device__ __forceinline__ void gbar(int phase)
{
    __syncthreads();
    if (threadIdx.x == 0) {
        __threadfence();
        if (atomicAdd(&g_bar_cnt, 1) == GRID - 1) {
            g_bar_cnt = 0;
            __threadfence();
            g_bar_flag = phase;
        } else {
            while (g_bar_flag < phase) { }
            __threadfence();
        }
    }
    __syncthreads();
}

__device__ __forceinline__ bool iou_gt(const float4 bi, const float ai, const float4 bj)
{
    const float ix1 = fmaxf(bi.x, bj.x);
    const float iy1 = fmaxf(bi.y, bj.y);
    const float ix2 = fminf(bi.z, bj.z);
    const float iy2 = fminf(bi.w, bj.w);
    const float iw = fmaxf(__fsub_rn(ix2, ix1), 0.0f);
    const float ih = fmaxf(__fsub_rn(iy2, iy1), 0.0f);
    const float inter = __fmul_rn(iw, ih);
    const float aj = __fmul_rn(__fsub_rn(bj.z, bj.x), __fsub_rn(bj.w, bj.y));
    const float uni = __fsub_rn(__fadd_rn(ai, aj), inter);
    return (uni > 0.0f) && (__fdiv_rn(inter, uni) > 0.5f);
}

extern __shared__ unsigned char dsm[];   // dynamic smem, aliased per phase

__global__ void __launch_bounds__(BLK) k_all(
    const float* __restrict__ x, float* __restrict__ out, int out_size)
{
    float*    s_sc  = reinterpret_cast<float*>(dsm);             // phase A: all NN scores
    float4*   s_bx  = reinterpret_cast<float4*>(dsm + BXOFF);    // phase B: M boxes
    uint32_t* smask = reinterpret_cast<uint32_t*>(dsm);          // phase C: full mask

    __shared__ uint32_t sdiag[32 * 32];
    __shared__ uint32_t s_keepw[32];
    __shared__ uint32_t s_kb[NN / 32];     // slow-path kept bitmap
    __shared__ int      s_mcnt;

    const int tid  = threadIdx.x;
    const int gtid = blockIdx.x * BLK + tid;
    const int lane = tid & 31;
    const int widx = tid >> 5;
    const int gw   = blockIdx.x * (BLK / 32) + widx;   // global warp id

    // ------ phase A: zero output; rank+decode+scatter directly (no compaction)
    if (tid == 0) s_mcnt = 0;
    for (int i = gtid; i < out_size; i += NTHR) out[i] = 0.0f;
    for (int i = tid; i < NN; i += BLK) s_sc[i] = x[i];
    __syncthreads();

    int nvalid = 0;
    for (int gid = gw; gid < NN; gid += NWARP) {
        const float s = s_sc[gid];             // warp-uniform broadcast
        if (!(s > THR)) continue;              // warp-uniform skip
        ++nvalid;
        // rank over raw scores: validity of j implied (s_j >= s > THR)
        int r = 0;
        #pragma unroll 8
        for (int j = lane; j < NN; j += 32) {
            const float sj = s_sc[j];
            r += (sj > s) || ((sj == s) && (j < gid));
        }
        r = __reduce_add_sync(FULLM, r);
        if (lane == 0) {
            const float fi = (float)(gid / P);
            const float fj = (float)(gid % P);
            const float bx = __fadd_rn(__fmul_rn(x[1 * NN + gid], 16.0f), __fmul_rn(fi, 16.0f));
            const float by = __fadd_rn(__fmul_rn(x[2 * NN + gid], 16.0f), __fmul_rn(fj, 16.0f));
            const float bw = __fmul_rn(x[3 * NN + gid], 1536.0f);
            const float bh = __fmul_rn(x[4 * NN + gid], 1536.0f);
            g_sc[r] = s;
            g_bx[r] = make_float4(rintf(bx), rintf(by),
                                  rintf(__fadd_rn(bw, bx)), rintf(__fadd_rn(bh, by)));
        }
    }
    if (lane == 0 && nvalid) atomicAdd(&s_mcnt, nvalid);
    __syncthreads();
    if (tid == 0 && s_mcnt) atomicAdd(&g_cnt, s_mcnt);
    gbar(1);

    // ------ phase B: suppression mask (smem boxes, ballot) -------------------
    const int M = g_cnt;
    if (M > 0 && M <= MAXM) {
        const int W = (M + 31) >> 5;
        for (int j = tid; j < M; j += BLK) s_bx[j] = g_bx[j];
        __syncthreads();
        for (int i = gw; i < M; i += NWARP) {
            const float4 bi = s_bx[i];
            const float  ai = __fmul_rn(__fsub_rn(bi.z, bi.x), __fsub_rn(bi.w, bi.y));
            uint32_t myword = 0u;
            for (int w = 0; w < W; ++w) {
                const int j = (w << 5) + lane;
                bool pred = false;
                if (j < M) pred = iou_gt(bi, ai, s_bx[j]);
                const uint32_t word = __ballot_sync(FULLM, pred);
                if (lane == w) myword = word;
            }
            g_mask32[i * 32 + lane] = (lane < W) ? myword : 0u;  // full 128B line
        }
    }
    gbar(2);

    // ------ phase C: greedy reduce (block 0 only) ----------------------------
    if (blockIdx.x != 0) return;
    const bool wk = (out_size >= 6 * NN);

    if (M > 0 && M <= MAXM) {
        const int W = (M + 31) >> 5;
        const int words = M * 32;

        // all 8 warps stage the full mask into dynamic smem (uint4 vectorized)
        {
            const uint4* __restrict__ src4 = reinterpret_cast<const uint4*>(g_mask32);
            uint4* dst4 = reinterpret_cast<uint4*>(smask);
            for (int t = tid; t < (words >> 2); t += BLK) dst4[t] = src4[t];
        }
        for (int idx = tid; idx < (W << 5); idx += BLK)
            sdiag[idx] = (idx < M) ? g_mask32[idx * 32 + (idx >> 5)] : 0u;
        __syncthreads();

        if (tid < 32) {
            const uint32_t mybit = 1u << lane;
            const uint32_t above = ~((2u << lane) - 1u);   // bits strictly > lane
            uint32_t rem = 0u;

            for (int w = 0; w < W; ++w) {
                const int base = w << 5;

                uint32_t buf[32];
                #pragma unroll
                for (int b = 0; b < 32; ++b)
                    buf[b] = smask[(base + b) * 32 + lane];

                const int nval = M - base;
                const uint32_t vmask = (nval >= 32) ? FULLM : ((1u << nval) - 1u);
                const uint32_t rem_w = __shfl_sync(FULLM, rem, w);
                const uint32_t cand  = (~rem_w) & vmask;
                const uint32_t d = sdiag[base + lane] & above;

                // Jacobi fixpoint (unroll 2 per convergence check);
                // prefix-stabilization guarantees the greedy fixpoint.
                uint32_t kept = cand;
                for (;;) {
                    uint32_t sup = __reduce_or_sync(FULLM, (kept & mybit) ? d : 0u);
                    const uint32_t k1 = cand & ~sup;
                    sup = __reduce_or_sync(FULLM, (k1 & mybit) ? d : 0u);
                    const uint32_t k2 = cand & ~sup;
                    if (k2 == k1) { kept = k2; break; }
                    if (k2 == kept) break;
                    kept = k2;
                }
                if (lane == 0) s_keepw[w] = kept;

                uint32_t acc = 0u;
                #pragma unroll
                for (int b = 0; b < 32; ++b)
                    acc |= (kept & (1u << b)) ? buf[b] : 0u;
                rem |= acc;
            }
        }
        __syncthreads();

        for (int i = tid; i < M; i += BLK) {
            if ((s_keepw[i >> 5] >> (i & 31)) & 1u) {
                const float4 bi = g_bx[i];
                out[i * 5 + 0] = g_sc[i];
                out[i * 5 + 1] = bi.x;
                out[i * 5 + 2] = bi.y;
                out[i * 5 + 3] = __fsub_rn(bi.z, bi.x);
                out[i * 5 + 4] = __fsub_rn(bi.w, bi.y);
                if (wk) out[5 * NN + i] = 1.0f;
            }
        }
    } else if (M > MAXM) {
        // correct-but-slow fallback (never expected: seed-fixed M ~ 922)
        for (int t = tid; t < NN / 32; t += BLK) s_kb[t] = 0u;
        __syncthreads();
        if (tid == 0) {
            for (int i = 0; i < M; ++i) {
                const float4 bi = g_bx[i];
                const float  ai = __fmul_rn(__fsub_rn(bi.z, bi.x), __fsub_rn(bi.w, bi.y));
                bool sup = false;
                for (int j = 0; j < i && !sup; ++j)
                    if ((s_kb[j >> 5] >> (j & 31)) & 1u)
                        sup = iou_gt(bi, ai, g_bx[j]);
                if (!sup) {
                    s_kb[i >> 5] |= 1u << (i & 31);
                    out[i * 5 + 0] = g_sc[i];
                    out[i * 5 + 1] = bi.x;
                    out[i * 5 + 2] = bi.y;
                    out[i * 5 + 3] = __fsub_rn(bi.z, bi.x);
                    out[i * 5 + 4] = __fsub_rn(bi.w, bi.y);
                    if (wk) out[5 * NN + i] = 1.0f;
                }
            }
        }
        __syncthreads();
    }

    // deterministic state for the next graph replay
    if (tid == 0) { g_cnt = 0; g_bar_flag = 0; }
}

// ---------------------------------------------------------------------------
extern "C" void kernel_launch(void* const* d_in, const int* in_sizes, int n_in,
                              void* d_out, int out_size)
{
    const float* x = (const float*)d_in[0];
    float* out = (float*)d_out;
    cudaFuncSetAttribute(k_all, cudaFuncAttributeMaxDynamicSharedMemorySize, DSMEM);
    k_all<<<GRID, BLK, DSMEM>>>(x, out, out_size);
}

// round 14
// speedup vs baseline: 1.3294x; 1.3287x over previous
#include <cuda_runtime.h>
#include <cuda_bf16.h>
#include <cstdint>

#define P     96
#define NN    9216
#define THR   0.9f
#define MAXM  1024                 // fast-path capacity (observed M ~ 922, fixed seed)
#define NWRD  288                  // NN/32 ballot words
#define FULLM 0xffffffffu
#define GRID  64
#define BLK   256
#define NTHR  (GRID * BLK)
#define NWARP (NTHR / 32)
#define DSMEM (MAXM * 32 * 4)      // 128KB dynamic smem (aliased per phase)

// device-global scratch (no runtime allocation allowed)
__device__ __align__(128) int          g_bar_cnt;   // own L2 line
__device__ __align__(128) volatile int g_bar_flag;  // own L2 line
__device__ float    g_sc[NN];
__device__ float4   g_bx[NN];
__device__ __align__(16) uint32_t g_mask32[MAXM * 32];  // row stride 32 = 128B line

// grid-wide barrier (all GRID blocks co-resident; GRID <= SM count)
__device__ __forceinline__ void gbar(int phase)
{
    __syncthreads();
    if (threadIdx.x == 0) {
        __threadfence();
        if (atomicAdd(&g_bar_cnt, 1) == GRID - 1) {
            g_bar_cnt = 0;
            __threadfence();
            g_bar_flag = phase;
        } else {
            while (g_bar_flag < phase) { }
            __threadfence();
        }
    }
    __syncthreads();
}

__device__ __forceinline__ bool iou_gt(const float4 bi, const float ai, const float4 bj)
{
    const float ix1 = fmaxf(bi.x, bj.x);
    const float iy1 = fmaxf(bi.y, bj.y);
    const float ix2 = fminf(bi.z, bj.z);
    const float iy2 = fminf(bi.w, bj.w);
    const float iw = fmaxf(__fsub_rn(ix2, ix1), 0.0f);
    const float ih = fmaxf(__fsub_rn(iy2, iy1), 0.0f);
    const float inter = __fmul_rn(iw, ih);
    const float aj = __fmul_rn(__fsub_rn(bj.z, bj.x), __fsub_rn(bj.w, bj.y));
    const float uni = __fsub_rn(__fadd_rn(ai, aj), inter);
    return (uni > 0.0f) && (__fdiv_rn(inter, uni) > 0.5f);
}

// decode box for flat index gid (mirrors reference op order; no FMA contraction)
__device__ __forceinline__ float4 decode_box(const float* __restrict__ x, int gid)
{
    const float fi = (float)(gid / P);
    const float fj = (float)(gid % P);
    const float bx = __fadd_rn(__fmul_rn(x[1 * NN + gid], 16.0f), __fmul_rn(fi, 16.0f));
    const float by = __fadd_rn(__fmul_rn(x[2 * NN + gid], 16.0f), __fmul_rn(fj, 16.0f));
    const float bw = __fmul_rn(x[3 * NN + gid], 1536.0f);
    const float bh = __fmul_rn(x[4 * NN + gid], 1536.0f);
    return make_float4(rintf(bx), rintf(by),
                       rintf(__fadd_rn(bw, bx)), rintf(__fadd_rn(bh, by)));
}

extern __shared__ unsigned char dsm[];   // dynamic smem, aliased per phase

__global__ void __launch_bounds__(BLK) k_all(
    const float* __restrict__ x, float* __restrict__ out, int out_size)
{
    // phase A aliases
    float*    s_sc  = reinterpret_cast<float*>(dsm);              // all NN scores (36KB)
    float*    s_cs  = reinterpret_cast<float*>(dsm + 36864);      // compacted scores (4KB)
    int*      s_cid = reinterpret_cast<int*>(dsm + 40960);        // compacted ids (4KB)
    // phase B alias
    float4*   s_bx  = reinterpret_cast<float4*>(dsm);             // M ranked boxes (16KB)
    // phase C alias
    uint32_t* smask = reinterpret_cast<uint32_t*>(dsm);           // full mask (128KB)

    __shared__ uint32_t s_wrd[NWRD];
    __shared__ int      s_pref[NWRD + 1];
    __shared__ uint32_t sdiag[32 * 32];
    __shared__ uint32_t s_keepw[32];
    __shared__ uint32_t s_kb[NN / 32];     // slow-path kept bitmap

    const int tid  = threadIdx.x;
    const int gtid = blockIdx.x * BLK + tid;
    const int lane = tid & 31;
    const int widx = tid >> 5;
    const int gw   = blockIdx.x * (BLK / 32) + widx;   // global warp id

    // ---- phase A: zero out; LOCAL compact (identical in every block); rank --
    for (int i = gtid; i < out_size; i += NTHR) out[i] = 0.0f;

    {   // stage all scores (vectorized)
        const float4* __restrict__ x4 = reinterpret_cast<const float4*>(x);
        float4* s4 = reinterpret_cast<float4*>(s_sc);
        for (int i = tid; i < NN / 4; i += BLK) s4[i] = x4[i];
    }
    __syncthreads();

    // ballot words
    for (int w = widx; w < NWRD; w += BLK / 32) {
        const uint32_t b = __ballot_sync(FULLM, s_sc[(w << 5) + lane] > THR);
        if (lane == 0) s_wrd[w] = b;
    }
    __syncthreads();

    // exclusive prefix over word popcounts (warp 0)
    if (widx == 0) {
        int run = 0;
        for (int c = 0; c < NWRD; c += 32) {
            const int pc = __popc(s_wrd[c + lane]);
            int sc = pc;
            #pragma unroll
            for (int o = 1; o < 32; o <<= 1) {
                const int n = __shfl_up_sync(FULLM, sc, o);
                if (lane >= o) sc += n;
            }
            s_pref[c + lane] = run + sc - pc;          // exclusive
            run += __shfl_sync(FULLM, sc, 31);
        }
        if (lane == 0) s_pref[NWRD] = run;             // = M
    }
    __syncthreads();
    const int M = s_pref[NWRD];

    // compact (stable, ascending gid)
    if (M <= MAXM) {
        for (int w = widx; w < NWRD; w += BLK / 32) {
            const uint32_t b = s_wrd[w];
            const int gid = (w << 5) + lane;
            if ((b >> lane) & 1u) {
                const int pos = s_pref[w] + __popc(b & ((1u << lane) - 1u));
                s_cs[pos]  = s_sc[gid];
                s_cid[pos] = gid;
            }
        }
        __syncthreads();

        // warp-per-entry rank (stable) + inline decode + scatter
        for (int t = gw; t < M; t += NWARP) {
            const float s  = s_cs[t];
            const int   id = s_cid[t];
            int r = 0;
            #pragma unroll 4
            for (int j = lane; j < M; j += 32) {
                const float sj = s_cs[j];
                const int   ij = s_cid[j];
                r += (sj > s) || ((sj == s) && (ij < id));
            }
            r = __reduce_add_sync(FULLM, r);
            if (lane == 0) { g_sc[r] = s; g_bx[r] = decode_box(x, id); }
        }
    } else {
        // fallback rank over raw scores (validity of j implied); never expected
        for (int gid = gw; gid < NN; gid += NWARP) {
            const float s = s_sc[gid];
            if (!(s > THR)) continue;
            int r = 0;
            for (int j = lane; j < NN; j += 32) {
                const float sj = s_sc[j];
                r += (sj > s) || ((sj == s) && (j < gid));
            }
            r = __reduce_add_sync(FULLM, r);
            if (lane == 0) { g_sc[r] = s; g_bx[r] = decode_box(x, gid); }
        }
    }
    gbar(1);

    // ---- phase B: suppression mask (smem boxes, ballot) ---------------------
    if (M > 0 && M <= MAXM) {
        const int W = (M + 31) >> 5;
        for (int j = tid; j < M; j += BLK) s_bx[j] = g_bx[j];
        __syncthreads();
        for (int i = gw; i < M; i += NWARP) {
            const float4 bi = s_bx[i];
            const float  ai = __fmul_rn(__fsub_rn(bi.z, bi.x), __fsub_rn(bi.w, bi.y));
            uint32_t myword = 0u;
            for (int w = 0; w < W; ++w) {
                const int j = (w << 5) + lane;
                bool pred = false;
                if (j < M) pred = iou_gt(bi, ai, s_bx[j]);
                const uint32_t word = __ballot_sync(FULLM, pred);
                if (lane == w) myword = word;
            }
            g_mask32[i * 32 + lane] = (lane < W) ? myword : 0u;  // full 128B line
        }
    }
    gbar(2);

    // ---- phase C: greedy reduce (block 0 only) ------------------------------
    if (blockIdx.x != 0) return;
    const bool wk = (out_size >= 6 * NN);

    if (M > 0 && M <= MAXM) {
        const int W = (M + 31) >> 5;
        const int words = M * 32;

        {   // all 8 warps stage the full mask into dynamic smem
            const uint4* __restrict__ src4 = reinterpret_cast<const uint4*>(g_mask32);
            uint4* dst4 = reinterpret_cast<uint4*>(smask);
            for (int t = tid; t < (words >> 2); t += BLK) dst4[t] = src4[t];
        }
        for (int idx = tid; idx < (W << 5); idx += BLK)
            sdiag[idx] = (idx < M) ? g_mask32[idx * 32 + (idx >> 5)] : 0u;
        __syncthreads();

        if (tid < 32) {
            const uint32_t mybit = 1u << lane;
            const uint32_t above = ~((2u << lane) - 1u);   // bits strictly > lane
            uint32_t rem = 0u;

            for (int w = 0; w < W; ++w) {
                const int base = w << 5;

                uint32_t buf[32];
                #pragma unroll
                for (int b = 0; b < 32; ++b)
                    buf[b] = smask[(base + b) * 32 + lane];

                const int nval = M - base;
                const uint32_t vmask = (nval >= 32) ? FULLM : ((1u << nval) - 1u);
                const uint32_t rem_w = __shfl_sync(FULLM, rem, w);
                const uint32_t cand  = (~rem_w) & vmask;
                const uint32_t d = sdiag[base + lane] & above;

                // Jacobi fixpoint (unroll 2 per convergence check);
                // prefix-stabilization guarantees the greedy fixpoint.
                uint32_t kept = cand;
                for (;;) {
                    uint32_t sup = __reduce_or_sync(FULLM, (kept & mybit) ? d : 0u);
                    const uint32_t k1 = cand & ~sup;
                    sup = __reduce_or_sync(FULLM, (k1 & mybit) ? d : 0u);
                    const uint32_t k2 = cand & ~sup;
                    if (k2 == k1) { kept = k2; break; }
                    if (k2 == kept) break;
                    kept = k2;
                }
                if (lane == 0) s_keepw[w] = kept;

                uint32_t acc = 0u;
                #pragma unroll
                for (int b = 0; b < 32; ++b)
                    acc |= (kept & (1u << b)) ? buf[b] : 0u;
                rem |= acc;
            }
        }
        __syncthreads();

        for (int i = tid; i < M; i += BLK) {
            if ((s_keepw[i >> 5] >> (i & 31)) & 1u) {
                const float4 bi = g_bx[i];
                out[i * 5 + 0] = g_sc[i];
                out[i * 5 + 1] = bi.x;
                out[i * 5 + 2] = bi.y;
                out[i * 5 + 3] = __fsub_rn(bi.z, bi.x);
                out[i * 5 + 4] = __fsub_rn(bi.w, bi.y);
                if (wk) out[5 * NN + i] = 1.0f;
            }
        }
    } else if (M > MAXM) {
        // correct-but-slow fallback (never expected: seed-fixed M ~ 922)
        for (int t = tid; t < NN / 32; t += BLK) s_kb[t] = 0u;
        __syncthreads();
        if (tid == 0) {
            for (int i = 0; i < M; ++i) {
                const float4 bi = g_bx[i];
                const float  ai = __fmul_rn(__fsub_rn(bi.z, bi.x), __fsub_rn(bi.w, bi.y));
                bool sup = false;
                for (int j = 0; j < i && !sup; ++j)
                    if ((s_kb[j >> 5] >> (j & 31)) & 1u)
                        sup = iou_gt(bi, ai, g_bx[j]);
                if (!sup) {
                    s_kb[i >> 5] |= 1u << (i & 31);
                    out[i * 5 + 0] = g_sc[i];
                    out[i * 5 + 1] = bi.x;
                    out[i * 5 + 2] = bi.y;
                    out[i * 5 + 3] = __fsub_rn(bi.z, bi.x);
                    out[i * 5 + 4] = __fsub_rn(bi.w, bi.y);
                    if (wk) out[5 * NN + i] = 1.0f;
                }
            }
        }
        __syncthreads();
    }

    // deterministic state for the next graph replay
    if (tid == 0) g_bar_flag = 0;
}

// ---------------------------------------------------------------------------
extern "C" void kernel_launch(void* const* d_in, const int* in_sizes, int n_in,
                              void* d_out, int out_size)
{
    const float* x = (const float*)d_in[0];
    float* out = (float*)d_out;
    cudaFuncSetAttribute(k_all, cudaFuncAttributeMaxDynamicSharedMemorySize, DSMEM);
    k_all<<<GRID, BLK, DSMEM>>>(x, out, out_size);
}